// round 1
// baseline (speedup 1.0000x reference)
#include <cuda_runtime.h>
#include <math.h>

#define MAX_N 100000
#define HID   32
#define IN_DIM 11

// Scratch (static __device__ — no allocation allowed)
__device__ float g_deg [MAX_N];
__device__ float g_dinv[MAX_N];
__device__ float g_y   [MAX_N * HID];   // dinv-prescaled transformed features
__device__ float g_agg [MAX_N * HID];   // scatter accumulator

// ---------------------------------------------------------------------------
// 1) init: deg = 1 (self loop), agg = 0
__global__ void init_kernel(int n) {
    int i = blockIdx.x * blockDim.x + threadIdx.x;
    if (i < n * HID) g_agg[i] = 0.f;
    if (i < n)       g_deg[i] = 1.f;
}

// 2) degree: deg[dst] += 1 over E edges
__global__ void degree_kernel(const int* __restrict__ dst, int E) {
    int e = blockIdx.x * blockDim.x + threadIdx.x;
    if (e < E) atomicAdd(&g_deg[dst[e]], 1.f);
}

// 3) y1 = dinv * (x @ W1); also store dinv.  One warp per node, lane = out ch.
__global__ void y1_kernel(const float* __restrict__ x,
                          const float* __restrict__ W1, int n) {
    __shared__ float sW[IN_DIM * HID];
    for (int i = threadIdx.x; i < IN_DIM * HID; i += blockDim.x) sW[i] = W1[i];
    __syncthreads();

    int warp = threadIdx.x >> 5, lane = threadIdx.x & 31;
    int node = blockIdx.x * (blockDim.x >> 5) + warp;
    if (node >= n) return;

    float xv = (lane < IN_DIM) ? x[node * IN_DIM + lane] : 0.f;
    float acc = 0.f;
#pragma unroll
    for (int k = 0; k < IN_DIM; k++) {
        float xk = __shfl_sync(0xffffffffu, xv, k);
        acc = fmaf(xk, sW[k * HID + lane], acc);
    }
    float dv = rsqrtf(g_deg[node]);
    if (lane == 0) g_dinv[node] = dv;
    g_y[node * HID + lane] = dv * acc;
}

// 4) scatter: agg[dst] += y[src].  8 lanes per edge, float4 per lane,
//    vector reduction (red.global.add.v4.f32) -> 8 red msgs / edge.
__global__ void scatter_kernel(const int* __restrict__ src,
                               const int* __restrict__ dst, int E) {
    int gwarp = (blockIdx.x * blockDim.x + threadIdx.x) >> 5;
    int lane  = threadIdx.x & 31;
    int e = gwarp * 4 + (lane >> 3);          // 4 edges per warp
    if (e >= E) return;
    int g = lane & 7;                          // float4 group within row
    int s = __ldg(src + e);
    int d = __ldg(dst + e);
    float4 v = __ldg(reinterpret_cast<const float4*>(g_y + s * HID) + g);
    float* ap = g_agg + d * HID + g * 4;
    asm volatile("red.global.add.v4.f32 [%0], {%1,%2,%3,%4};"
                 :: "l"(ap), "f"(v.x), "f"(v.y), "f"(v.z), "f"(v.w)
                 : "memory");
}

// 5) mid: h1 = relu(dinv*(agg + y_self) + b1);  y2 = dinv*(h1 @ W2);
//    also reset agg row to 0 for reuse by scatter #2.
__global__ void mid_kernel(const float* __restrict__ W2,
                           const float* __restrict__ b1, int n) {
    __shared__ float sW[HID * HID];
    for (int i = threadIdx.x; i < HID * HID; i += blockDim.x) sW[i] = W2[i];
    __syncthreads();

    int warp = threadIdx.x >> 5, lane = threadIdx.x & 31;
    int node = blockIdx.x * (blockDim.x >> 5) + warp;
    if (node >= n) return;

    int base = node * HID + lane;
    float a  = g_agg[base];
    float yv = g_y[base];
    float dv = g_dinv[node];
    float h  = fmaxf(fmaf(dv, a + yv, b1[lane]), 0.f);
    g_agg[base] = 0.f;                        // reset for layer-2 scatter

    float acc = 0.f;
#pragma unroll
    for (int k = 0; k < HID; k++) {
        float hk = __shfl_sync(0xffffffffu, h, k);
        acc = fmaf(hk, sW[k * HID + lane], acc);
    }
    g_y[base] = dv * acc;
}

// 6) final: h2 = relu(dinv*(agg + y_self) + b2);
//    t = elu(h2 @ Wo1 + bo1) [16];  out = t @ Wo2 + bo2 [scalar]
__global__ void final_kernel(const float* __restrict__ Wo1,
                             const float* __restrict__ bo1,
                             const float* __restrict__ Wo2,
                             const float* __restrict__ bo2,
                             const float* __restrict__ b2,
                             float* __restrict__ out, int n) {
    __shared__ float sW[HID * 16];
    __shared__ float sW2[16];
    for (int i = threadIdx.x; i < HID * 16; i += blockDim.x) sW[i] = Wo1[i];
    if (threadIdx.x < 16) sW2[threadIdx.x] = Wo2[threadIdx.x];
    __syncthreads();

    int warp = threadIdx.x >> 5, lane = threadIdx.x & 31;
    int node = blockIdx.x * (blockDim.x >> 5) + warp;
    if (node >= n) return;

    int base = node * HID + lane;
    float a  = g_agg[base];
    float yv = g_y[base];
    float dv = g_dinv[node];
    float h  = fmaxf(fmaf(dv, a + yv, b2[lane]), 0.f);

    int j = lane & 15;
    float acc = 0.f;
#pragma unroll
    for (int k = 0; k < HID; k++) {
        float hk = __shfl_sync(0xffffffffu, h, k);
        acc = fmaf(hk, sW[k * 16 + j], acc);
    }
    // lanes 0..15 hold the 16 hidden units (lanes 16..31 duplicate them)
    float t = acc + bo1[j];
    t = (t > 0.f) ? t : expm1f(t);
    float p = (lane < 16) ? t * sW2[j] : 0.f;
    p += __shfl_down_sync(0xffffffffu, p, 8);
    p += __shfl_down_sync(0xffffffffu, p, 4);
    p += __shfl_down_sync(0xffffffffu, p, 2);
    p += __shfl_down_sync(0xffffffffu, p, 1);
    if (lane == 0) out[node] = p + bo2[0];
}

// ---------------------------------------------------------------------------
extern "C" void kernel_launch(void* const* d_in, const int* in_sizes, int n_in,
                              void* d_out, int out_size) {
    const float* x   = (const float*)d_in[0];
    const int*   ei  = (const int*)  d_in[1];   // [2, E] row-major
    // d_in[2] = batch (unused)
    const float* W1  = (const float*)d_in[3];
    const float* b1  = (const float*)d_in[4];
    const float* W2  = (const float*)d_in[5];
    const float* b2  = (const float*)d_in[6];
    const float* Wo1 = (const float*)d_in[7];
    const float* bo1 = (const float*)d_in[8];
    const float* Wo2 = (const float*)d_in[9];
    const float* bo2 = (const float*)d_in[10];
    float* out = (float*)d_out;

    int n = in_sizes[0] / IN_DIM;
    int E = in_sizes[1] / 2;
    const int* src = ei;
    const int* dst = ei + E;

    const int TPB = 256;
    int nodes_per_blk = TPB / 32;

    // 1) init
    init_kernel<<<(n * HID + TPB - 1) / TPB, TPB>>>(n);
    // 2) degree
    degree_kernel<<<(E + TPB - 1) / TPB, TPB>>>(dst, E);
    // 3) y1
    y1_kernel<<<(n + nodes_per_blk - 1) / nodes_per_blk, TPB>>>(x, W1, n);
    // 4) scatter layer 1  (4 edges per warp)
    int edges_per_blk = (TPB / 32) * 4;
    scatter_kernel<<<(E + edges_per_blk - 1) / edges_per_blk, TPB>>>(src, dst, E);
    // 5) mid (finish layer1, compute y2, reset agg)
    mid_kernel<<<(n + nodes_per_blk - 1) / nodes_per_blk, TPB>>>(W2, b1, n);
    // 6) scatter layer 2
    scatter_kernel<<<(E + edges_per_blk - 1) / edges_per_blk, TPB>>>(src, dst, E);
    // 7) final
    final_kernel<<<(n + nodes_per_blk - 1) / nodes_per_blk, TPB>>>(
        Wo1, bo1, Wo2, bo2, b2, out, n);
}

// round 2
// speedup vs baseline: 1.2108x; 1.2108x over previous
#include <cuda_runtime.h>
#include <math.h>

#define MAX_N   100000
#define MAX_E   3200000
#define HID     32
#define IN_DIM  11
#define SCAN_BLK 256

// ---------------------------------------------------------------------------
// Static scratch (no allocation allowed).
// INVARIANT: g_deg is all-zero at kernel_launch entry. It is zero at program
// start (static init) and agg2_kernel resets it at the end of every call.
__device__ int   g_deg   [MAX_N];        // in-degree (excl. self loop)
__device__ float g_dinv  [MAX_N];        // rsqrt(deg+1)
__device__ int   g_rowloc[MAX_N];        // block-local exclusive scan of deg
__device__ int   g_bsum  [1024];         // per-block sums
__device__ int   g_boff  [1024];         // exclusive scan of block sums
__device__ int   g_row   [MAX_N];        // CSR row start (by dst)
__device__ int   g_cur   [MAX_N];        // fill cursor
__device__ int   g_col   [MAX_E];        // CSR column (src) indices
__device__ float g_y     [MAX_N * HID];  // dinv-prescaled features, layer 1
__device__ float g_y2    [MAX_N * HID];  // dinv-prescaled features, layer 2

// ---------------------------------------------------------------------------
// 1) degree histogram over dst
__global__ void degree_kernel(const int* __restrict__ dst, int E) {
    int e = blockIdx.x * blockDim.x + threadIdx.x;
    if (e < E) atomicAdd(&g_deg[dst[e]], 1);
}

// 2a) per-block inclusive scan of degrees -> local exclusive + block sums
__global__ void scan1_kernel(int n) {
    __shared__ int s[SCAN_BLK];
    int tid = threadIdx.x;
    int i = blockIdx.x * SCAN_BLK + tid;
    int v = (i < n) ? g_deg[i] : 0;
    s[tid] = v; __syncthreads();
#pragma unroll
    for (int off = 1; off < SCAN_BLK; off <<= 1) {
        int t = (tid >= off) ? s[tid - off] : 0;
        __syncthreads();
        s[tid] += t;
        __syncthreads();
    }
    if (i < n) g_rowloc[i] = s[tid] - v;                 // exclusive
    if (tid == SCAN_BLK - 1) g_bsum[blockIdx.x] = s[tid]; // block total
}

// 2b) single-block exclusive scan of block sums (nblk <= 1024)
__global__ void scan2_kernel(int nblk) {
    __shared__ int s[1024];
    int tid = threadIdx.x;
    int v = (tid < nblk) ? g_bsum[tid] : 0;
    s[tid] = v; __syncthreads();
#pragma unroll
    for (int off = 1; off < 1024; off <<= 1) {
        int t = (tid >= off) ? s[tid - off] : 0;
        __syncthreads();
        s[tid] += t;
        __syncthreads();
    }
    if (tid < nblk) g_boff[tid] = s[tid] - v;
}

// 3) y1 = dinv * (x @ W1); also finalize row offsets + cursors + dinv.
//    One warp per node, lane = output channel.
__global__ void y1_kernel(const float* __restrict__ x,
                          const float* __restrict__ W1, int n) {
    __shared__ float sW[IN_DIM * HID];
    for (int i = threadIdx.x; i < IN_DIM * HID; i += blockDim.x) sW[i] = W1[i];
    __syncthreads();

    int warp = threadIdx.x >> 5, lane = threadIdx.x & 31;
    int node = blockIdx.x * (blockDim.x >> 5) + warp;
    if (node >= n) return;

    float xv = (lane < IN_DIM) ? x[node * IN_DIM + lane] : 0.f;
    float acc = 0.f;
#pragma unroll
    for (int k = 0; k < IN_DIM; k++) {
        float xk = __shfl_sync(0xffffffffu, xv, k);
        acc = fmaf(xk, sW[k * HID + lane], acc);
    }
    int   dg = g_deg[node];
    float dv = rsqrtf((float)(dg + 1));       // +1 for self loop
    if (lane == 0) {
        g_dinv[node] = dv;
        int r = g_rowloc[node] + g_boff[node / SCAN_BLK];
        g_row[node] = r;
        g_cur[node] = r;
    }
    g_y[node * HID + lane] = dv * acc;
}

// 4) fill CSR: col[cursor[dst]++] = src
__global__ void fill_kernel(const int* __restrict__ src,
                            const int* __restrict__ dst, int E) {
    int e = blockIdx.x * blockDim.x + threadIdx.x;
    if (e < E) {
        int d = dst[e];
        int pos = atomicAdd(&g_cur[d], 1);
        g_col[pos] = src[e];
    }
}

// ---------------------------------------------------------------------------
// Gather-aggregate helper: warp-per-node, lane = channel, batches of 8 edges
// for MLP=8. Returns sum over incoming y rows + self row.
__device__ __forceinline__ float gather_row(const float* __restrict__ ybuf,
                                            int node, int lane) {
    float acc = ybuf[node * HID + lane];      // self loop term
    int beg = g_row[node];
    int cnt = g_deg[node];
    int i = 0;
    for (; i + 8 <= cnt; i += 8) {
        int myidx = 0;
        if (lane < 8) myidx = __ldg(&g_col[beg + i + lane]);
        float v0, v1, v2, v3, v4, v5, v6, v7;
        int s0 = __shfl_sync(0xffffffffu, myidx, 0);
        int s1 = __shfl_sync(0xffffffffu, myidx, 1);
        int s2 = __shfl_sync(0xffffffffu, myidx, 2);
        int s3 = __shfl_sync(0xffffffffu, myidx, 3);
        int s4 = __shfl_sync(0xffffffffu, myidx, 4);
        int s5 = __shfl_sync(0xffffffffu, myidx, 5);
        int s6 = __shfl_sync(0xffffffffu, myidx, 6);
        int s7 = __shfl_sync(0xffffffffu, myidx, 7);
        v0 = __ldcg(ybuf + s0 * HID + lane);
        v1 = __ldcg(ybuf + s1 * HID + lane);
        v2 = __ldcg(ybuf + s2 * HID + lane);
        v3 = __ldcg(ybuf + s3 * HID + lane);
        v4 = __ldcg(ybuf + s4 * HID + lane);
        v5 = __ldcg(ybuf + s5 * HID + lane);
        v6 = __ldcg(ybuf + s6 * HID + lane);
        v7 = __ldcg(ybuf + s7 * HID + lane);
        acc += ((v0 + v1) + (v2 + v3)) + ((v4 + v5) + (v6 + v7));
    }
    for (; i < cnt; i++) {
        int s = __ldg(&g_col[beg + i]);
        acc += __ldcg(ybuf + s * HID + lane);
    }
    return acc;
}

// 5) layer-1 aggregation fused with relu epilogue and W2 transform:
//    h1 = relu(dinv*(sum + self) + b1);  y2 = dinv*(h1 @ W2)
__global__ void agg1_kernel(const float* __restrict__ b1,
                            const float* __restrict__ W2, int n) {
    __shared__ float sW[HID * HID];
    for (int i = threadIdx.x; i < HID * HID; i += blockDim.x) sW[i] = W2[i];
    __syncthreads();

    int warp = threadIdx.x >> 5, lane = threadIdx.x & 31;
    int node = blockIdx.x * (blockDim.x >> 5) + warp;
    if (node >= n) return;

    float acc = gather_row(g_y, node, lane);
    float dv  = g_dinv[node];
    float h   = fmaxf(fmaf(dv, acc, b1[lane]), 0.f);

    float o = 0.f;
#pragma unroll
    for (int k = 0; k < HID; k++) {
        float hk = __shfl_sync(0xffffffffu, h, k);
        o = fmaf(hk, sW[k * HID + lane], o);
    }
    g_y2[node * HID + lane] = dv * o;
}

// 6) layer-2 aggregation fused with relu + MLP head. Resets g_deg (invariant).
__global__ void agg2_kernel(const float* __restrict__ b2,
                            const float* __restrict__ Wo1,
                            const float* __restrict__ bo1,
                            const float* __restrict__ Wo2,
                            const float* __restrict__ bo2,
                            float* __restrict__ out, int n) {
    __shared__ float sW[HID * 16];
    __shared__ float sW2[16];
    for (int i = threadIdx.x; i < HID * 16; i += blockDim.x) sW[i] = Wo1[i];
    if (threadIdx.x < 16) sW2[threadIdx.x] = Wo2[threadIdx.x];
    __syncthreads();

    int warp = threadIdx.x >> 5, lane = threadIdx.x & 31;
    int node = blockIdx.x * (blockDim.x >> 5) + warp;
    if (node >= n) return;

    float acc = gather_row(g_y2, node, lane);
    float dv  = g_dinv[node];
    float h   = fmaxf(fmaf(dv, acc, b2[lane]), 0.f);

    int j = lane & 15;
    float t = 0.f;
#pragma unroll
    for (int k = 0; k < HID; k++) {
        float hk = __shfl_sync(0xffffffffu, h, k);
        t = fmaf(hk, sW[k * 16 + j], t);
    }
    t += bo1[j];
    t = (t > 0.f) ? t : expm1f(t);          // elu
    float p = (lane < 16) ? t * sW2[j] : 0.f;
    p += __shfl_down_sync(0xffffffffu, p, 8);
    p += __shfl_down_sync(0xffffffffu, p, 4);
    p += __shfl_down_sync(0xffffffffu, p, 2);
    p += __shfl_down_sync(0xffffffffu, p, 1);
    if (lane == 0) {
        out[node] = p + bo2[0];
        g_deg[node] = 0;                    // restore invariant for next call
    }
}

// ---------------------------------------------------------------------------
extern "C" void kernel_launch(void* const* d_in, const int* in_sizes, int n_in,
                              void* d_out, int out_size) {
    const float* x   = (const float*)d_in[0];
    const int*   ei  = (const int*)  d_in[1];   // [2, E] row-major
    // d_in[2] = batch (unused)
    const float* W1  = (const float*)d_in[3];
    const float* b1  = (const float*)d_in[4];
    const float* W2  = (const float*)d_in[5];
    const float* b2  = (const float*)d_in[6];
    const float* Wo1 = (const float*)d_in[7];
    const float* bo1 = (const float*)d_in[8];
    const float* Wo2 = (const float*)d_in[9];
    const float* bo2 = (const float*)d_in[10];
    float* out = (float*)d_out;

    int n = in_sizes[0] / IN_DIM;
    int E = in_sizes[1] / 2;
    const int* src = ei;
    const int* dst = ei + E;

    const int TPB = 256;
    int nodes_per_blk = TPB / 32;
    int node_grid = (n + nodes_per_blk - 1) / nodes_per_blk;
    int nblk = (n + SCAN_BLK - 1) / SCAN_BLK;

    // 1) degree histogram (g_deg is zero on entry, by invariant)
    degree_kernel<<<(E + TPB - 1) / TPB, TPB>>>(dst, E);
    // 2) scan degrees -> row offsets
    scan1_kernel<<<nblk, SCAN_BLK>>>(n);
    scan2_kernel<<<1, 1024>>>(nblk);
    // 3) y1 = dinv * (x @ W1); finalize row/cursor/dinv
    y1_kernel<<<node_grid, TPB>>>(x, W1, n);
    // 4) CSR fill
    fill_kernel<<<(E + TPB - 1) / TPB, TPB>>>(src, dst, E);
    // 5) aggregation layer 1 (fused relu + W2)
    agg1_kernel<<<node_grid, TPB>>>(b1, W2, n);
    // 6) aggregation layer 2 (fused relu + MLP head; resets g_deg)
    agg2_kernel<<<node_grid, TPB>>>(b2, Wo1, bo1, Wo2, bo2, out, n);
}

// round 5
// speedup vs baseline: 1.2361x; 1.0209x over previous
#include <cuda_runtime.h>
#include <math.h>

#define MAX_N   100000
#define MAX_E   3200000
#define HID     32
#define IN_DIM  11
#define SCAN_BLK 256

// ---------------------------------------------------------------------------
// Static scratch (no allocation allowed).
// INVARIANT: g_deg is all-zero at kernel_launch entry (zero at static init;
// agg2_kernel resets it at the end of every call).
__device__ int   g_deg   [MAX_N];
__device__ float g_dinv  [MAX_N];
__device__ int   g_rowloc[MAX_N];
__device__ int   g_bsum  [1024];
__device__ int   g_boff  [1024];
__device__ int   g_row   [MAX_N];
__device__ int   g_cur   [MAX_N];
__device__ int   g_col   [MAX_E];
__device__ float g_y     [MAX_N * HID];
__device__ float g_y2    [MAX_N * HID];

// ---------------------------------------------------------------------------
// 1) degree histogram over dst (4 edges per thread, int4 loads)
__global__ void degree_kernel(const int* __restrict__ dst, int E) {
    int t = blockIdx.x * blockDim.x + threadIdx.x;
    int e = t * 4;
    if (e + 3 < E) {
        int4 d = __ldg(reinterpret_cast<const int4*>(dst) + t);
        atomicAdd(&g_deg[d.x], 1);
        atomicAdd(&g_deg[d.y], 1);
        atomicAdd(&g_deg[d.z], 1);
        atomicAdd(&g_deg[d.w], 1);
    } else {
        for (int k = e; k < E; k++) atomicAdd(&g_deg[dst[k]], 1);
    }
}

// 2a) per-block inclusive scan of degrees -> local exclusive + block sums
__global__ void scan1_kernel(int n) {
    __shared__ int s[SCAN_BLK];
    int tid = threadIdx.x;
    int i = blockIdx.x * SCAN_BLK + tid;
    int v = (i < n) ? g_deg[i] : 0;
    s[tid] = v; __syncthreads();
#pragma unroll
    for (int off = 1; off < SCAN_BLK; off <<= 1) {
        int t = (tid >= off) ? s[tid - off] : 0;
        __syncthreads();
        s[tid] += t;
        __syncthreads();
    }
    if (i < n) g_rowloc[i] = s[tid] - v;
    if (tid == SCAN_BLK - 1) g_bsum[blockIdx.x] = s[tid];
}

// 2b) single-block exclusive scan of block sums (nblk <= 1024)
__global__ void scan2_kernel(int nblk) {
    __shared__ int s[1024];
    int tid = threadIdx.x;
    int v = (tid < nblk) ? g_bsum[tid] : 0;
    s[tid] = v; __syncthreads();
#pragma unroll
    for (int off = 1; off < 1024; off <<= 1) {
        int t = (tid >= off) ? s[tid - off] : 0;
        __syncthreads();
        s[tid] += t;
        __syncthreads();
    }
    if (tid < nblk) g_boff[tid] = s[tid] - v;
}

// 3) y1 = dinv * (x @ W1); finalize row/cursor/dinv. 4 nodes per warp.
__global__ void y1_kernel(const float* __restrict__ x,
                          const float* __restrict__ W1, int n) {
    __shared__ float sW[IN_DIM * HID];
    for (int i = threadIdx.x; i < IN_DIM * HID; i += blockDim.x) sW[i] = W1[i];
    __syncthreads();

    int warp = threadIdx.x >> 5, lane = threadIdx.x & 31;
    int node0 = (blockIdx.x * (blockDim.x >> 5) + warp) * 4;
    if (node0 >= n) return;

    int base = node0 * IN_DIM;
    int lim = n * IN_DIM;
    float a = (base + lane < lim) ? x[base + lane] : 0.f;
    float b = (lane < 12 && base + 32 + lane < lim) ? x[base + 32 + lane] : 0.f;

#pragma unroll
    for (int j = 0; j < 4; j++) {
        int node = node0 + j;
        if (node >= n) break;
        float acc = 0.f;
#pragma unroll
        for (int k = 0; k < IN_DIM; k++) {
            int flat = j * IN_DIM + k;
            float xk = (flat < 32) ? __shfl_sync(0xffffffffu, a, flat)
                                   : __shfl_sync(0xffffffffu, b, flat - 32);
            acc = fmaf(xk, sW[k * HID + lane], acc);
        }
        float dv = rsqrtf((float)(g_deg[node] + 1));
        if (lane == 0) {
            g_dinv[node] = dv;
            int r = g_rowloc[node] + g_boff[node / SCAN_BLK];
            g_row[node] = r;
            g_cur[node] = r;
        }
        g_y[node * HID + lane] = dv * acc;
    }
}

// 4) fill CSR (4 edges per thread, int4 loads)
__global__ void fill_kernel(const int* __restrict__ src,
                            const int* __restrict__ dst, int E) {
    int t = blockIdx.x * blockDim.x + threadIdx.x;
    int e = t * 4;
    if (e + 3 < E) {
        int4 d = __ldg(reinterpret_cast<const int4*>(dst) + t);
        int4 s = __ldg(reinterpret_cast<const int4*>(src) + t);
        g_col[atomicAdd(&g_cur[d.x], 1)] = s.x;
        g_col[atomicAdd(&g_cur[d.y], 1)] = s.y;
        g_col[atomicAdd(&g_cur[d.z], 1)] = s.z;
        g_col[atomicAdd(&g_cur[d.w], 1)] = s.w;
    } else {
        for (int k = e; k < E; k++)
            g_col[atomicAdd(&g_cur[dst[k]], 1)] = src[k];
    }
}

// ---------------------------------------------------------------------------
// Gather: warp-per-node, float4 per lane, 4 edge rows per LDG.128 instruction,
// 16 edges per batch with double-buffered index loads. Returns per-lane scalar
// h_pre = sum over incoming rows + self row, for channel c = lane.
__device__ __forceinline__ float gather_row(const float* __restrict__ ybuf,
                                            int node, int lane) {
    int beg = g_row[node];
    int cnt = g_deg[node];
    int g   = lane & 7;       // float4 group within row
    int sub = lane >> 3;      // which edge of the quad this lane handles

    float4 acc = make_float4(0.f, 0.f, 0.f, 0.f);

    int i = 0;
    int idx = (cnt >= 16 && lane < 16) ? __ldg(&g_col[beg + lane]) : 0;
    for (; i + 16 <= cnt; i += 16) {
        int nidx = (i + 32 <= cnt && lane < 16)
                 ? __ldg(&g_col[beg + i + 16 + lane]) : 0;
#pragma unroll
        for (int it = 0; it < 4; it++) {
            int s = __shfl_sync(0xffffffffu, idx, it * 4 + sub);
            float4 v = __ldcg(reinterpret_cast<const float4*>(ybuf + s * HID) + g);
            acc.x += v.x; acc.y += v.y; acc.z += v.z; acc.w += v.w;
        }
        idx = nidx;
    }

    int rem = cnt - i;
    if (rem > 0) {
        int tidx = (lane < rem) ? __ldg(&g_col[beg + i + lane]) : 0;
        for (int it = 0; it * 4 < rem; it++) {
            int e = it * 4 + sub;
            int s = __shfl_sync(0xffffffffu, tidx, e & 15);
            if (e < rem) {
                float4 v = __ldcg(reinterpret_cast<const float4*>(ybuf + s * HID) + g);
                acc.x += v.x; acc.y += v.y; acc.z += v.z; acc.w += v.w;
            }
        }
    }

    // reduce across the 4 edge-subgroups (lanes differing in bits 3,4)
#pragma unroll
    for (int m = 8; m <= 16; m <<= 1) {
        acc.x += __shfl_xor_sync(0xffffffffu, acc.x, m);
        acc.y += __shfl_xor_sync(0xffffffffu, acc.y, m);
        acc.z += __shfl_xor_sync(0xffffffffu, acc.z, m);
        acc.w += __shfl_xor_sync(0xffffffffu, acc.w, m);
    }

    // transpose: channel c = lane lives in component (lane&3) of group (lane>>2)
    int gsrc = lane >> 2;
    float cx = __shfl_sync(0xffffffffu, acc.x, gsrc);
    float cy = __shfl_sync(0xffffffffu, acc.y, gsrc);
    float cz = __shfl_sync(0xffffffffu, acc.z, gsrc);
    float cw = __shfl_sync(0xffffffffu, acc.w, gsrc);
    int sel = lane & 3;
    float v = (sel == 0) ? cx : (sel == 1) ? cy : (sel == 2) ? cz : cw;

    // self-loop term (coalesced 128B load)
    return v + ybuf[node * HID + lane];
}

// 5) layer-1 aggregation + relu + W2 transform: y2 = dinv*(relu(dinv*sum+b1) @ W2)
__global__ void agg1_kernel(const float* __restrict__ b1,
                            const float* __restrict__ W2, int n) {
    __shared__ float sW[HID * HID];
    for (int i = threadIdx.x; i < HID * HID; i += blockDim.x) sW[i] = W2[i];
    __syncthreads();

    int warp = threadIdx.x >> 5, lane = threadIdx.x & 31;
    int node = blockIdx.x * (blockDim.x >> 5) + warp;
    if (node >= n) return;

    float acc = gather_row(g_y, node, lane);
    float dv  = g_dinv[node];
    float h   = fmaxf(fmaf(dv, acc, b1[lane]), 0.f);

    float o = 0.f;
#pragma unroll
    for (int k = 0; k < HID; k++) {
        float hk = __shfl_sync(0xffffffffu, h, k);
        o = fmaf(hk, sW[k * HID + lane], o);
    }
    g_y2[node * HID + lane] = dv * o;
}

// 6) layer-2 aggregation + relu + MLP head. Resets g_deg (invariant).
__global__ void agg2_kernel(const float* __restrict__ b2,
                            const float* __restrict__ Wo1,
                            const float* __restrict__ bo1,
                            const float* __restrict__ Wo2,
                            const float* __restrict__ bo2,
                            float* __restrict__ out, int n) {
    __shared__ float sW[HID * 16];
    __shared__ float sW2[16];
    for (int i = threadIdx.x; i < HID * 16; i += blockDim.x) sW[i] = Wo1[i];
    if (threadIdx.x < 16) sW2[threadIdx.x] = Wo2[threadIdx.x];
    __syncthreads();

    int warp = threadIdx.x >> 5, lane = threadIdx.x & 31;
    int node = blockIdx.x * (blockDim.x >> 5) + warp;
    if (node >= n) return;

    float acc = gather_row(g_y2, node, lane);
    float dv  = g_dinv[node];
    float h   = fmaxf(fmaf(dv, acc, b2[lane]), 0.f);

    int j = lane & 15;
    float t = 0.f;
#pragma unroll
    for (int k = 0; k < HID; k++) {
        float hk = __shfl_sync(0xffffffffu, h, k);
        t = fmaf(hk, sW[k * 16 + j], t);
    }
    t += bo1[j];
    t = (t > 0.f) ? t : expm1f(t);          // elu
    float p = (lane < 16) ? t * sW2[j] : 0.f;
    p += __shfl_down_sync(0xffffffffu, p, 8);
    p += __shfl_down_sync(0xffffffffu, p, 4);
    p += __shfl_down_sync(0xffffffffu, p, 2);
    p += __shfl_down_sync(0xffffffffu, p, 1);
    if (lane == 0) {
        out[node] = p + bo2[0];
        g_deg[node] = 0;                    // restore invariant for next call
    }
}

// ---------------------------------------------------------------------------
extern "C" void kernel_launch(void* const* d_in, const int* in_sizes, int n_in,
                              void* d_out, int out_size) {
    const float* x   = (const float*)d_in[0];
    const int*   ei  = (const int*)  d_in[1];   // [2, E] row-major
    const float* W1  = (const float*)d_in[3];
    const float* b1  = (const float*)d_in[4];
    const float* W2  = (const float*)d_in[5];
    const float* b2  = (const float*)d_in[6];
    const float* Wo1 = (const float*)d_in[7];
    const float* bo1 = (const float*)d_in[8];
    const float* Wo2 = (const float*)d_in[9];
    const float* bo2 = (const float*)d_in[10];
    float* out = (float*)d_out;

    int n = in_sizes[0] / IN_DIM;
    int E = in_sizes[1] / 2;
    const int* src = ei;
    const int* dst = ei + E;

    const int TPB = 256;
    int node_grid = (n + (TPB / 32) - 1) / (TPB / 32);          // warp per node
    int quad_grid = (n + (TPB / 32) * 4 - 1) / ((TPB / 32) * 4); // 4 nodes/warp
    int nblk = (n + SCAN_BLK - 1) / SCAN_BLK;
    int e4_grid = ((E + 3) / 4 + TPB - 1) / TPB;

    degree_kernel<<<e4_grid, TPB>>>(dst, E);
    scan1_kernel<<<nblk, SCAN_BLK>>>(n);
    scan2_kernel<<<1, 1024>>>(nblk);
    y1_kernel<<<quad_grid, TPB>>>(x, W1, n);
    fill_kernel<<<e4_grid, TPB>>>(src, dst, E);
    agg1_kernel<<<node_grid, TPB>>>(b1, W2, n);
    agg2_kernel<<<node_grid, TPB>>>(b2, Wo1, bo1, Wo2, bo2, out, n);
}

// round 6
// speedup vs baseline: 1.2372x; 1.0009x over previous
#include <cuda_runtime.h>
#include <math.h>

#define MAX_N   100000
#define MAX_E   3200000
#define HID     32
#define IN_DIM  11
#define SCAN_BLK 256

// ---------------------------------------------------------------------------
// Static scratch (no allocation allowed).
// INVARIANT: g_deg is all-zero at kernel_launch entry (zero at static init;
// agg2_kernel resets it at the end of every call).
__device__ int   g_deg   [MAX_N];
__device__ float g_dinv  [MAX_N];
__device__ int   g_rowloc[MAX_N];
__device__ int   g_bsum  [1024];
__device__ int   g_boff  [1024];
__device__ int   g_row   [MAX_N];
__device__ int   g_cur   [MAX_N];
__device__ int   g_col   [MAX_E];
__device__ float g_y     [MAX_N * HID];
__device__ float g_y2    [MAX_N * HID];

// ---------------------------------------------------------------------------
// 1) degree histogram over dst (4 edges per thread, int4 loads)
__global__ void degree_kernel(const int* __restrict__ dst, int E) {
    int t = blockIdx.x * blockDim.x + threadIdx.x;
    int e = t * 4;
    if (e + 3 < E) {
        int4 d = __ldg(reinterpret_cast<const int4*>(dst) + t);
        atomicAdd(&g_deg[d.x], 1);
        atomicAdd(&g_deg[d.y], 1);
        atomicAdd(&g_deg[d.z], 1);
        atomicAdd(&g_deg[d.w], 1);
    } else {
        for (int k = e; k < E; k++) atomicAdd(&g_deg[dst[k]], 1);
    }
}

// 2a) per-block inclusive scan of degrees -> local exclusive + block sums
__global__ void scan1_kernel(int n) {
    __shared__ int s[SCAN_BLK];
    int tid = threadIdx.x;
    int i = blockIdx.x * SCAN_BLK + tid;
    int v = (i < n) ? g_deg[i] : 0;
    s[tid] = v; __syncthreads();
#pragma unroll
    for (int off = 1; off < SCAN_BLK; off <<= 1) {
        int t = (tid >= off) ? s[tid - off] : 0;
        __syncthreads();
        s[tid] += t;
        __syncthreads();
    }
    if (i < n) g_rowloc[i] = s[tid] - v;
    if (tid == SCAN_BLK - 1) g_bsum[blockIdx.x] = s[tid];
}

// 2b) single-block exclusive scan of block sums (nblk <= 1024)
__global__ void scan2_kernel(int nblk) {
    __shared__ int s[1024];
    int tid = threadIdx.x;
    int v = (tid < nblk) ? g_bsum[tid] : 0;
    s[tid] = v; __syncthreads();
#pragma unroll
    for (int off = 1; off < 1024; off <<= 1) {
        int t = (tid >= off) ? s[tid - off] : 0;
        __syncthreads();
        s[tid] += t;
        __syncthreads();
    }
    if (tid < nblk) g_boff[tid] = s[tid] - v;
}

// 3) y1 = dinv * (x @ W1); finalize row/cursor/dinv. 4 nodes per warp.
__global__ void y1_kernel(const float* __restrict__ x,
                          const float* __restrict__ W1, int n) {
    __shared__ float sW[IN_DIM * HID];
    for (int i = threadIdx.x; i < IN_DIM * HID; i += blockDim.x) sW[i] = W1[i];
    __syncthreads();

    int warp = threadIdx.x >> 5, lane = threadIdx.x & 31;
    int node0 = (blockIdx.x * (blockDim.x >> 5) + warp) * 4;
    if (node0 >= n) return;

    int base = node0 * IN_DIM;
    int lim = n * IN_DIM;
    float a = (base + lane < lim) ? x[base + lane] : 0.f;
    float b = (lane < 12 && base + 32 + lane < lim) ? x[base + 32 + lane] : 0.f;

#pragma unroll
    for (int j = 0; j < 4; j++) {
        int node = node0 + j;
        if (node >= n) break;
        float acc = 0.f;
#pragma unroll
        for (int k = 0; k < IN_DIM; k++) {
            int flat = j * IN_DIM + k;
            float xk = (flat < 32) ? __shfl_sync(0xffffffffu, a, flat)
                                   : __shfl_sync(0xffffffffu, b, flat - 32);
            acc = fmaf(xk, sW[k * HID + lane], acc);
        }
        float dv = rsqrtf((float)(g_deg[node] + 1));
        if (lane == 0) {
            g_dinv[node] = dv;
            int r = g_rowloc[node] + g_boff[node / SCAN_BLK];
            g_row[node] = r;
            g_cur[node] = r;
        }
        g_y[node * HID + lane] = dv * acc;
    }
}

// 4) fill CSR (4 edges per thread, int4 loads)
__global__ void fill_kernel(const int* __restrict__ src,
                            const int* __restrict__ dst, int E) {
    int t = blockIdx.x * blockDim.x + threadIdx.x;
    int e = t * 4;
    if (e + 3 < E) {
        int4 d = __ldg(reinterpret_cast<const int4*>(dst) + t);
        int4 s = __ldg(reinterpret_cast<const int4*>(src) + t);
        g_col[atomicAdd(&g_cur[d.x], 1)] = s.x;
        g_col[atomicAdd(&g_cur[d.y], 1)] = s.y;
        g_col[atomicAdd(&g_cur[d.z], 1)] = s.z;
        g_col[atomicAdd(&g_cur[d.w], 1)] = s.w;
    } else {
        for (int k = e; k < E; k++)
            g_col[atomicAdd(&g_cur[dst[k]], 1)] = src[k];
    }
}

// ---------------------------------------------------------------------------
// Gather: warp-per-node, float4 per lane, 4 edge rows per LDG.128 instruction,
// 16 edges per batch with double-buffered index loads. Returns per-lane scalar
// h_pre = sum over incoming rows + self row, for channel c = lane.
__device__ __forceinline__ float gather_row(const float* __restrict__ ybuf,
                                            int node, int lane) {
    int beg = g_row[node];
    int cnt = g_deg[node];
    int g   = lane & 7;       // float4 group within row
    int sub = lane >> 3;      // which edge of the quad this lane handles

    float4 acc = make_float4(0.f, 0.f, 0.f, 0.f);

    int i = 0;
    int idx = (cnt >= 16 && lane < 16) ? __ldg(&g_col[beg + lane]) : 0;
    for (; i + 16 <= cnt; i += 16) {
        int nidx = (i + 32 <= cnt && lane < 16)
                 ? __ldg(&g_col[beg + i + 16 + lane]) : 0;
#pragma unroll
        for (int it = 0; it < 4; it++) {
            int s = __shfl_sync(0xffffffffu, idx, it * 4 + sub);
            float4 v = __ldcg(reinterpret_cast<const float4*>(ybuf + s * HID) + g);
            acc.x += v.x; acc.y += v.y; acc.z += v.z; acc.w += v.w;
        }
        idx = nidx;
    }

    int rem = cnt - i;
    if (rem > 0) {
        int tidx = (lane < rem) ? __ldg(&g_col[beg + i + lane]) : 0;
        for (int it = 0; it * 4 < rem; it++) {
            int e = it * 4 + sub;
            int s = __shfl_sync(0xffffffffu, tidx, e & 15);
            if (e < rem) {
                float4 v = __ldcg(reinterpret_cast<const float4*>(ybuf + s * HID) + g);
                acc.x += v.x; acc.y += v.y; acc.z += v.z; acc.w += v.w;
            }
        }
    }

    // reduce across the 4 edge-subgroups (lanes differing in bits 3,4)
#pragma unroll
    for (int m = 8; m <= 16; m <<= 1) {
        acc.x += __shfl_xor_sync(0xffffffffu, acc.x, m);
        acc.y += __shfl_xor_sync(0xffffffffu, acc.y, m);
        acc.z += __shfl_xor_sync(0xffffffffu, acc.z, m);
        acc.w += __shfl_xor_sync(0xffffffffu, acc.w, m);
    }

    // transpose: channel c = lane lives in component (lane&3) of group (lane>>2)
    int gsrc = lane >> 2;
    float cx = __shfl_sync(0xffffffffu, acc.x, gsrc);
    float cy = __shfl_sync(0xffffffffu, acc.y, gsrc);
    float cz = __shfl_sync(0xffffffffu, acc.z, gsrc);
    float cw = __shfl_sync(0xffffffffu, acc.w, gsrc);
    int sel = lane & 3;
    float v = (sel == 0) ? cx : (sel == 1) ? cy : (sel == 2) ? cz : cw;

    // self-loop term (coalesced 128B load)
    return v + ybuf[node * HID + lane];
}

// 5) layer-1 aggregation + relu + W2 transform: y2 = dinv*(relu(dinv*sum+b1) @ W2)
__global__ void agg1_kernel(const float* __restrict__ b1,
                            const float* __restrict__ W2, int n) {
    __shared__ float sW[HID * HID];
    for (int i = threadIdx.x; i < HID * HID; i += blockDim.x) sW[i] = W2[i];
    __syncthreads();

    int warp = threadIdx.x >> 5, lane = threadIdx.x & 31;
    int node = blockIdx.x * (blockDim.x >> 5) + warp;
    if (node >= n) return;

    float acc = gather_row(g_y, node, lane);
    float dv  = g_dinv[node];
    float h   = fmaxf(fmaf(dv, acc, b1[lane]), 0.f);

    float o = 0.f;
#pragma unroll
    for (int k = 0; k < HID; k++) {
        float hk = __shfl_sync(0xffffffffu, h, k);
        o = fmaf(hk, sW[k * HID + lane], o);
    }
    g_y2[node * HID + lane] = dv * o;
}

// 6) layer-2 aggregation + relu + MLP head. Resets g_deg (invariant).
__global__ void agg2_kernel(const float* __restrict__ b2,
                            const float* __restrict__ Wo1,
                            const float* __restrict__ bo1,
                            const float* __restrict__ Wo2,
                            const float* __restrict__ bo2,
                            float* __restrict__ out, int n) {
    __shared__ float sW[HID * 16];
    __shared__ float sW2[16];
    for (int i = threadIdx.x; i < HID * 16; i += blockDim.x) sW[i] = Wo1[i];
    if (threadIdx.x < 16) sW2[threadIdx.x] = Wo2[threadIdx.x];
    __syncthreads();

    int warp = threadIdx.x >> 5, lane = threadIdx.x & 31;
    int node = blockIdx.x * (blockDim.x >> 5) + warp;
    if (node >= n) return;

    float acc = gather_row(g_y2, node, lane);
    float dv  = g_dinv[node];
    float h   = fmaxf(fmaf(dv, acc, b2[lane]), 0.f);

    int j = lane & 15;
    float t = 0.f;
#pragma unroll
    for (int k = 0; k < HID; k++) {
        float hk = __shfl_sync(0xffffffffu, h, k);
        t = fmaf(hk, sW[k * 16 + j], t);
    }
    t += bo1[j];
    t = (t > 0.f) ? t : expm1f(t);          // elu
    float p = (lane < 16) ? t * sW2[j] : 0.f;
    p += __shfl_down_sync(0xffffffffu, p, 8);
    p += __shfl_down_sync(0xffffffffu, p, 4);
    p += __shfl_down_sync(0xffffffffu, p, 2);
    p += __shfl_down_sync(0xffffffffu, p, 1);
    if (lane == 0) {
        out[node] = p + bo2[0];
        g_deg[node] = 0;                    // restore invariant for next call
    }
}

// ---------------------------------------------------------------------------
extern "C" void kernel_launch(void* const* d_in, const int* in_sizes, int n_in,
                              void* d_out, int out_size) {
    const float* x   = (const float*)d_in[0];
    const int*   ei  = (const int*)  d_in[1];   // [2, E] row-major
    const float* W1  = (const float*)d_in[3];
    const float* b1  = (const float*)d_in[4];
    const float* W2  = (const float*)d_in[5];
    const float* b2  = (const float*)d_in[6];
    const float* Wo1 = (const float*)d_in[7];
    const float* bo1 = (const float*)d_in[8];
    const float* Wo2 = (const float*)d_in[9];
    const float* bo2 = (const float*)d_in[10];
    float* out = (float*)d_out;

    int n = in_sizes[0] / IN_DIM;
    int E = in_sizes[1] / 2;
    const int* src = ei;
    const int* dst = ei + E;

    const int TPB = 256;
    int node_grid = (n + (TPB / 32) - 1) / (TPB / 32);          // warp per node
    int quad_grid = (n + (TPB / 32) * 4 - 1) / ((TPB / 32) * 4); // 4 nodes/warp
    int nblk = (n + SCAN_BLK - 1) / SCAN_BLK;
    int e4_grid = ((E + 3) / 4 + TPB - 1) / TPB;

    degree_kernel<<<e4_grid, TPB>>>(dst, E);
    scan1_kernel<<<nblk, SCAN_BLK>>>(n);
    scan2_kernel<<<1, 1024>>>(nblk);
    y1_kernel<<<quad_grid, TPB>>>(x, W1, n);
    fill_kernel<<<e4_grid, TPB>>>(src, dst, E);
    agg1_kernel<<<node_grid, TPB>>>(b1, W2, n);
    agg2_kernel<<<node_grid, TPB>>>(b2, Wo1, bo1, Wo2, bo2, out, n);
}

// round 7
// speedup vs baseline: 1.2382x; 1.0008x over previous
#include <cuda_runtime.h>
#include <math.h>

#define MAX_N   100000
#define MAX_E   3200000
#define HID     32
#define IN_DIM  11
#define SCAN_BLK 256

// ---------------------------------------------------------------------------
// Static scratch (no allocation allowed).
// INVARIANT: g_deg is all-zero at kernel_launch entry (zero at static init;
// agg2_kernel resets it at the end of every call).
__device__ int   g_deg   [MAX_N];
__device__ float g_dinv  [MAX_N];
__device__ int   g_rowloc[MAX_N];
__device__ int   g_bsum  [1024];
__device__ int   g_boff  [1024];
__device__ int   g_row   [MAX_N];
__device__ int   g_cur   [MAX_N];
__device__ int   g_col   [MAX_E];
__device__ float g_y     [MAX_N * HID];
__device__ float g_y2    [MAX_N * HID];

// ---------------------------------------------------------------------------
// 1) degree histogram over dst (4 edges per thread, int4 loads)
__global__ void degree_kernel(const int* __restrict__ dst, int E) {
    int t = blockIdx.x * blockDim.x + threadIdx.x;
    int e = t * 4;
    if (e + 3 < E) {
        int4 d = __ldg(reinterpret_cast<const int4*>(dst) + t);
        atomicAdd(&g_deg[d.x], 1);
        atomicAdd(&g_deg[d.y], 1);
        atomicAdd(&g_deg[d.z], 1);
        atomicAdd(&g_deg[d.w], 1);
    } else {
        for (int k = e; k < E; k++) atomicAdd(&g_deg[dst[k]], 1);
    }
}

// 2a) per-block inclusive scan of degrees -> local exclusive + block sums
__global__ void scan1_kernel(int n) {
    __shared__ int s[SCAN_BLK];
    int tid = threadIdx.x;
    int i = blockIdx.x * SCAN_BLK + tid;
    int v = (i < n) ? g_deg[i] : 0;
    s[tid] = v; __syncthreads();
#pragma unroll
    for (int off = 1; off < SCAN_BLK; off <<= 1) {
        int t = (tid >= off) ? s[tid - off] : 0;
        __syncthreads();
        s[tid] += t;
        __syncthreads();
    }
    if (i < n) g_rowloc[i] = s[tid] - v;
    if (tid == SCAN_BLK - 1) g_bsum[blockIdx.x] = s[tid];
}

// 2b) single-block exclusive scan of block sums (nblk <= 1024)
__global__ void scan2_kernel(int nblk) {
    __shared__ int s[1024];
    int tid = threadIdx.x;
    int v = (tid < nblk) ? g_bsum[tid] : 0;
    s[tid] = v; __syncthreads();
#pragma unroll
    for (int off = 1; off < 1024; off <<= 1) {
        int t = (tid >= off) ? s[tid - off] : 0;
        __syncthreads();
        s[tid] += t;
        __syncthreads();
    }
    if (tid < nblk) g_boff[tid] = s[tid] - v;
}

// 3) y1 = dinv * (x @ W1); finalize row/cursor/dinv. 4 nodes per warp.
__global__ void y1_kernel(const float* __restrict__ x,
                          const float* __restrict__ W1, int n) {
    __shared__ float sW[IN_DIM * HID];
    for (int i = threadIdx.x; i < IN_DIM * HID; i += blockDim.x) sW[i] = W1[i];
    __syncthreads();

    int warp = threadIdx.x >> 5, lane = threadIdx.x & 31;
    int node0 = (blockIdx.x * (blockDim.x >> 5) + warp) * 4;
    if (node0 >= n) return;

    int base = node0 * IN_DIM;
    int lim = n * IN_DIM;
    float a = (base + lane < lim) ? x[base + lane] : 0.f;
    float b = (lane < 12 && base + 32 + lane < lim) ? x[base + 32 + lane] : 0.f;

#pragma unroll
    for (int j = 0; j < 4; j++) {
        int node = node0 + j;
        if (node >= n) break;
        float acc = 0.f;
#pragma unroll
        for (int k = 0; k < IN_DIM; k++) {
            int flat = j * IN_DIM + k;
            float xk = (flat < 32) ? __shfl_sync(0xffffffffu, a, flat)
                                   : __shfl_sync(0xffffffffu, b, flat - 32);
            acc = fmaf(xk, sW[k * HID + lane], acc);
        }
        float dv = rsqrtf((float)(g_deg[node] + 1));
        if (lane == 0) {
            g_dinv[node] = dv;
            int r = g_rowloc[node] + g_boff[node / SCAN_BLK];
            g_row[node] = r;
            g_cur[node] = r;
        }
        g_y[node * HID + lane] = dv * acc;
    }
}

// 4) fill CSR (4 edges per thread, int4 loads)
__global__ void fill_kernel(const int* __restrict__ src,
                            const int* __restrict__ dst, int E) {
    int t = blockIdx.x * blockDim.x + threadIdx.x;
    int e = t * 4;
    if (e + 3 < E) {
        int4 d = __ldg(reinterpret_cast<const int4*>(dst) + t);
        int4 s = __ldg(reinterpret_cast<const int4*>(src) + t);
        g_col[atomicAdd(&g_cur[d.x], 1)] = s.x;
        g_col[atomicAdd(&g_cur[d.y], 1)] = s.y;
        g_col[atomicAdd(&g_cur[d.z], 1)] = s.z;
        g_col[atomicAdd(&g_cur[d.w], 1)] = s.w;
    } else {
        for (int k = e; k < E; k++)
            g_col[atomicAdd(&g_cur[dst[k]], 1)] = src[k];
    }
}

// ---------------------------------------------------------------------------
// Gather: warp-per-node, float4 per lane, 4 edge rows per LDG.128 instruction,
// 16 edges per batch with double-buffered index loads. Returns per-lane scalar
// h_pre = sum over incoming rows + self row, for channel c = lane.
__device__ __forceinline__ float gather_row(const float* __restrict__ ybuf,
                                            int node, int lane) {
    int beg = g_row[node];
    int cnt = g_deg[node];
    int g   = lane & 7;       // float4 group within row
    int sub = lane >> 3;      // which edge of the quad this lane handles

    float4 acc = make_float4(0.f, 0.f, 0.f, 0.f);

    int i = 0;
    int idx = (cnt >= 16 && lane < 16) ? __ldg(&g_col[beg + lane]) : 0;
    for (; i + 16 <= cnt; i += 16) {
        int nidx = (i + 32 <= cnt && lane < 16)
                 ? __ldg(&g_col[beg + i + 16 + lane]) : 0;
#pragma unroll
        for (int it = 0; it < 4; it++) {
            int s = __shfl_sync(0xffffffffu, idx, it * 4 + sub);
            float4 v = __ldcg(reinterpret_cast<const float4*>(ybuf + s * HID) + g);
            acc.x += v.x; acc.y += v.y; acc.z += v.z; acc.w += v.w;
        }
        idx = nidx;
    }

    int rem = cnt - i;
    if (rem > 0) {
        int tidx = (lane < rem) ? __ldg(&g_col[beg + i + lane]) : 0;
        for (int it = 0; it * 4 < rem; it++) {
            int e = it * 4 + sub;
            int s = __shfl_sync(0xffffffffu, tidx, e & 15);
            if (e < rem) {
                float4 v = __ldcg(reinterpret_cast<const float4*>(ybuf + s * HID) + g);
                acc.x += v.x; acc.y += v.y; acc.z += v.z; acc.w += v.w;
            }
        }
    }

    // reduce across the 4 edge-subgroups (lanes differing in bits 3,4)
#pragma unroll
    for (int m = 8; m <= 16; m <<= 1) {
        acc.x += __shfl_xor_sync(0xffffffffu, acc.x, m);
        acc.y += __shfl_xor_sync(0xffffffffu, acc.y, m);
        acc.z += __shfl_xor_sync(0xffffffffu, acc.z, m);
        acc.w += __shfl_xor_sync(0xffffffffu, acc.w, m);
    }

    // transpose: channel c = lane lives in component (lane&3) of group (lane>>2)
    int gsrc = lane >> 2;
    float cx = __shfl_sync(0xffffffffu, acc.x, gsrc);
    float cy = __shfl_sync(0xffffffffu, acc.y, gsrc);
    float cz = __shfl_sync(0xffffffffu, acc.z, gsrc);
    float cw = __shfl_sync(0xffffffffu, acc.w, gsrc);
    int sel = lane & 3;
    float v = (sel == 0) ? cx : (sel == 1) ? cy : (sel == 2) ? cz : cw;

    // self-loop term (coalesced 128B load)
    return v + ybuf[node * HID + lane];
}

// 5) layer-1 aggregation + relu + W2 transform: y2 = dinv*(relu(dinv*sum+b1) @ W2)
__global__ void agg1_kernel(const float* __restrict__ b1,
                            const float* __restrict__ W2, int n) {
    __shared__ float sW[HID * HID];
    for (int i = threadIdx.x; i < HID * HID; i += blockDim.x) sW[i] = W2[i];
    __syncthreads();

    int warp = threadIdx.x >> 5, lane = threadIdx.x & 31;
    int node = blockIdx.x * (blockDim.x >> 5) + warp;
    if (node >= n) return;

    float acc = gather_row(g_y, node, lane);
    float dv  = g_dinv[node];
    float h   = fmaxf(fmaf(dv, acc, b1[lane]), 0.f);

    float o = 0.f;
#pragma unroll
    for (int k = 0; k < HID; k++) {
        float hk = __shfl_sync(0xffffffffu, h, k);
        o = fmaf(hk, sW[k * HID + lane], o);
    }
    g_y2[node * HID + lane] = dv * o;
}

// 6) layer-2 aggregation + relu + MLP head. Resets g_deg (invariant).
__global__ void agg2_kernel(const float* __restrict__ b2,
                            const float* __restrict__ Wo1,
                            const float* __restrict__ bo1,
                            const float* __restrict__ Wo2,
                            const float* __restrict__ bo2,
                            float* __restrict__ out, int n) {
    __shared__ float sW[HID * 16];
    __shared__ float sW2[16];
    for (int i = threadIdx.x; i < HID * 16; i += blockDim.x) sW[i] = Wo1[i];
    if (threadIdx.x < 16) sW2[threadIdx.x] = Wo2[threadIdx.x];
    __syncthreads();

    int warp = threadIdx.x >> 5, lane = threadIdx.x & 31;
    int node = blockIdx.x * (blockDim.x >> 5) + warp;
    if (node >= n) return;

    float acc = gather_row(g_y2, node, lane);
    float dv  = g_dinv[node];
    float h   = fmaxf(fmaf(dv, acc, b2[lane]), 0.f);

    int j = lane & 15;
    float t = 0.f;
#pragma unroll
    for (int k = 0; k < HID; k++) {
        float hk = __shfl_sync(0xffffffffu, h, k);
        t = fmaf(hk, sW[k * 16 + j], t);
    }
    t += bo1[j];
    t = (t > 0.f) ? t : expm1f(t);          // elu
    float p = (lane < 16) ? t * sW2[j] : 0.f;
    p += __shfl_down_sync(0xffffffffu, p, 8);
    p += __shfl_down_sync(0xffffffffu, p, 4);
    p += __shfl_down_sync(0xffffffffu, p, 2);
    p += __shfl_down_sync(0xffffffffu, p, 1);
    if (lane == 0) {
        out[node] = p + bo2[0];
        g_deg[node] = 0;                    // restore invariant for next call
    }
}

// ---------------------------------------------------------------------------
extern "C" void kernel_launch(void* const* d_in, const int* in_sizes, int n_in,
                              void* d_out, int out_size) {
    const float* x   = (const float*)d_in[0];
    const int*   ei  = (const int*)  d_in[1];   // [2, E] row-major
    const float* W1  = (const float*)d_in[3];
    const float* b1  = (const float*)d_in[4];
    const float* W2  = (const float*)d_in[5];
    const float* b2  = (const float*)d_in[6];
    const float* Wo1 = (const float*)d_in[7];
    const float* bo1 = (const float*)d_in[8];
    const float* Wo2 = (const float*)d_in[9];
    const float* bo2 = (const float*)d_in[10];
    float* out = (float*)d_out;

    int n = in_sizes[0] / IN_DIM;
    int E = in_sizes[1] / 2;
    const int* src = ei;
    const int* dst = ei + E;

    const int TPB = 256;
    int node_grid = (n + (TPB / 32) - 1) / (TPB / 32);          // warp per node
    int quad_grid = (n + (TPB / 32) * 4 - 1) / ((TPB / 32) * 4); // 4 nodes/warp
    int nblk = (n + SCAN_BLK - 1) / SCAN_BLK;
    int e4_grid = ((E + 3) / 4 + TPB - 1) / TPB;

    degree_kernel<<<e4_grid, TPB>>>(dst, E);
    scan1_kernel<<<nblk, SCAN_BLK>>>(n);
    scan2_kernel<<<1, 1024>>>(nblk);
    y1_kernel<<<quad_grid, TPB>>>(x, W1, n);
    fill_kernel<<<e4_grid, TPB>>>(src, dst, E);
    agg1_kernel<<<node_grid, TPB>>>(b1, W2, n);
    agg2_kernel<<<node_grid, TPB>>>(b2, Wo1, bo1, Wo2, bo2, out, n);
}